// round 7
// baseline (speedup 1.0000x reference)
#include <cuda_runtime.h>
#include <cuda_fp16.h>

// LightGCN propagation, gather formulation, fp16 intermediates:
//   e0 = concat(user_emb, item_emb)           (N = 300000, D = 64)
//   e_{l+1}[r] = sum_{edges e: rows[e]==r} vals[e] * e_l[cols[e]]
//   out = (e0 + e1 + e2 + e3) / 4
//
// 5 launches total: prep (zero cnt + e0->half), build (padded CSR, width 32),
// gather x2 (half->half), gather_final (fused mean, fp32 e0). Overflow edges
// (deg > 32, expected ~0.5 total) are folded into the gather kernels via a
// per-warp scan of a tiny spill list — no extra launches, exact result.

#define DIM      64
#define DIM2     32              // half2 per row
#define PAD_W    32              // padded CSR width (deg ~ Poisson(13.3))
#define NMAX     300000
#define OVF_CAP  4096
#define TPB      256

// ---- static scratch (alloc-free rule) -------------------------------------
__device__ int     g_cnt[NMAX];                       // per-row degree/cursor
__device__ uint2   g_list[(size_t)NMAX * PAD_W];      // {col, val_bits} 76.8MB
__device__ int     g_ovf_cnt;
__device__ int4    g_ovf[OVF_CAP];                    // {row, col, val_bits, 0}
__device__ __half2 g_h0[(size_t)NMAX * DIM2];         // e0 (half)
__device__ __half2 g_h1[(size_t)NMAX * DIM2];         // e1 (half)
__device__ __half2 g_h2[(size_t)NMAX * DIM2];         // e2 (half)

// ---- fused: zero counters + convert e0 -> half ----------------------------
__global__ void lg_prep(const float2* __restrict__ user,
                        const float2* __restrict__ item,
                        int n_user2, int n2, int n_rows) {
    int i = blockIdx.x * blockDim.x + threadIdx.x;
    if (i < n_rows) g_cnt[i] = 0;
    if (i == 0) g_ovf_cnt = 0;
    if (i >= n2) return;
    float2 v = (i < n_user2) ? user[i] : item[i - n_user2];
    g_h0[i] = __float22half2_rn(v);
}

// ---- bucket edges into padded CSR -----------------------------------------
__global__ void lg_build(const int* __restrict__ rows,
                         const int* __restrict__ cols,
                         const float* __restrict__ vals, int nnz) {
    int e = blockIdx.x * blockDim.x + threadIdx.x;
    if (e >= nnz) return;
    int   r = rows[e];
    int   c = cols[e];
    float v = vals[e];
    int pos = atomicAdd(&g_cnt[r], 1);
    if (pos < PAD_W) {
        g_list[(size_t)r * PAD_W + pos] = make_uint2((unsigned)c, __float_as_uint(v));
    } else {
        int o = atomicAdd(&g_ovf_cnt, 1);
        if (o < OVF_CAP) g_ovf[o] = make_int4(r, c, __float_as_int(v), 0);
    }
}

// ---- per-row gather core: fp32 accumulate from half source ----------------
// deg <= PAD_W = 32 -> single entry load, no outer tiling. Spilled edges
// (deg > 32) are picked up from the tiny overflow list (uniform scan).
__device__ __forceinline__ float2 row_gather(const __half2* __restrict__ src,
                                             int row, int lane) {
    int deg = g_cnt[row];
    int nb  = min(deg, PAD_W);

    uint2 ent = (lane < nb) ? g_list[(size_t)row * PAD_W + lane]
                            : make_uint2(0u, 0u);
    float2 acc = make_float2(0.f, 0.f);

    #pragma unroll 8
    for (int j = 0; j < nb; j++) {
        int   c = __shfl_sync(0xffffffff, (int)ent.x, j);
        float v = __uint_as_float(__shfl_sync(0xffffffff, ent.y, j));
        float2 x = __half22float2(src[(size_t)c * DIM2 + lane]);
        acc.x += v * x.x;
        acc.y += v * x.y;
    }

    int novf = g_ovf_cnt;                 // broadcast hit; 0 in practice
    if (novf > 0) {
        if (novf > OVF_CAP) novf = OVF_CAP;
        for (int k = 0; k < novf; k++) {
            int4 rec = g_ovf[k];
            if (rec.x == row) {
                float v = __int_as_float(rec.z);
                float2 x = __half22float2(src[(size_t)rec.y * DIM2 + lane]);
                acc.x += v * x.x;
                acc.y += v * x.y;
            }
        }
    }
    return acc;
}

// ---- gather SpMM into a half buffer ---------------------------------------
__global__ void lg_gather_h(const __half2* __restrict__ src,
                            __half2* __restrict__ dst, int n_rows) {
    int warp = (int)((blockIdx.x * (unsigned)blockDim.x + threadIdx.x) >> 5);
    int lane = threadIdx.x & 31;
    if (warp >= n_rows) return;
    float2 acc = row_gather(src, warp, lane);
    dst[(size_t)warp * DIM2 + lane] = __float22half2_rn(acc);
}

// ---- layer-3 gather fused with the final mean -----------------------------
__global__ void lg_gather_final(const float* __restrict__ user,
                                const float* __restrict__ item, int n_user,
                                const __half2* __restrict__ e1,
                                const __half2* __restrict__ e2,
                                float* __restrict__ out, int n_rows) {
    int warp = (int)((blockIdx.x * (unsigned)blockDim.x + threadIdx.x) >> 5);
    int lane = threadIdx.x & 31;
    if (warp >= n_rows) return;
    float2 acc = row_gather(e2, warp, lane);              // e3 in fp32 regs

    const float* b0 = (warp < n_user) ? user + (size_t)warp * DIM
                                      : item + (size_t)(warp - n_user) * DIM;
    float2 v0 = *reinterpret_cast<const float2*>(b0 + 2 * lane);
    float2 v1 = __half22float2(e1[(size_t)warp * DIM2 + lane]);
    float2 v2 = __half22float2(e2[(size_t)warp * DIM2 + lane]);

    float2 r;
    r.x = (v0.x + v1.x + v2.x + acc.x) * 0.25f;
    r.y = (v0.y + v1.y + v2.y + acc.y) * 0.25f;
    *reinterpret_cast<float2*>(out + (size_t)warp * DIM + 2 * lane) = r;
}

extern "C" void kernel_launch(void* const* d_in, const int* in_sizes, int n_in,
                              void* d_out, int out_size) {
    const float* user = (const float*)d_in[0];
    const float* item = (const float*)d_in[1];
    const float* vals = (const float*)d_in[2];
    const int*   rows = (const int*)d_in[3];
    const int*   cols = (const int*)d_in[4];

    int n_user  = in_sizes[0] / DIM;
    int n_item  = in_sizes[1] / DIM;
    int nnz     = in_sizes[2];
    int n_total = n_user + n_item;
    int n2      = n_total * DIM2;

    float* out = (float*)d_out;

    __half2* h0; __half2* h1; __half2* h2;
    cudaGetSymbolAddress((void**)&h0, g_h0);
    cudaGetSymbolAddress((void**)&h1, g_h1);
    cudaGetSymbolAddress((void**)&h2, g_h2);

    int prep_blocks   = (n2 + TPB - 1) / TPB;
    int build_blocks  = (nnz + TPB - 1) / TPB;
    int gather_blocks = (n_total * 32 + TPB - 1) / TPB;   // 1 warp per row

    lg_prep<<<prep_blocks, TPB>>>((const float2*)user, (const float2*)item,
                                  n_user * DIM2, n2, n_total);
    lg_build<<<build_blocks, TPB>>>(rows, cols, vals, nnz);

    lg_gather_h<<<gather_blocks, TPB>>>(h0, h1, n_total);        // e1
    lg_gather_h<<<gather_blocks, TPB>>>(h1, h2, n_total);        // e2
    lg_gather_final<<<gather_blocks, TPB>>>(user, item, n_user,  // e3 + mean
                                            h1, h2, out, n_total);
}